// round 1
// baseline (speedup 1.0000x reference)
#include <cuda_runtime.h>
#include <math.h>
#include <stdint.h>

#define VOCAB   32000
#define DDIM    1024
#define NEXP    16
#define TOPK    2
#define BTOK    2048
#define SLEN    128
#define HDIM    2048
#define LN_EPS  1e-5f
#define NROWS   (BTOK*TOPK)   // 4096 routed rows

// ---------------- scratch (device globals; no allocation) ----------------
__device__ float g_h[BTOK * DDIM];              // pooled embeddings (fp32 exact)
__device__ int   g_counts[NEXP];
__device__ int   g_offsets[NEXP];
__device__ int   g_cursor[NEXP];
__device__ int   g_top_e[NROWS];
__device__ float g_top_p[NROWS];
__device__ int   g_row_token[NROWS];
__device__ float g_row_wgt[NROWS];
__device__ int   g_row_slot[NROWS];
__device__ float g_c1[NROWS * HDIM];            // 33.5MB intermediate
__device__ float g_parts[TOPK * BTOK * DDIM];   // per-slot weighted outputs

// ---------------- small helpers ----------------
__device__ __forceinline__ unsigned f2tf32(float x) {
    unsigned y;
    asm("cvt.rna.tf32.f32 %0, %1;" : "=r"(y) : "f"(x));
    return y;
}
__device__ __forceinline__ void cp_async16(unsigned dst, const void* src) {
    asm volatile("cp.async.cg.shared.global [%0], [%1], 16;\n" :: "r"(dst), "l"(src));
}
__device__ __forceinline__ void cp_commit() { asm volatile("cp.async.commit_group;\n"); }
template<int N> __device__ __forceinline__ void cp_wait() {
    asm volatile("cp.async.wait_group %0;\n" :: "n"(N));
}
__device__ __forceinline__ void mma_tf32(float c[4], const unsigned a[4], const unsigned b[2]) {
    asm volatile(
        "mma.sync.aligned.m16n8k8.row.col.f32.tf32.tf32.f32 "
        "{%0,%1,%2,%3}, {%4,%5,%6,%7}, {%8,%9}, {%0,%1,%2,%3};\n"
        : "+f"(c[0]), "+f"(c[1]), "+f"(c[2]), "+f"(c[3])
        : "r"(a[0]), "r"(a[1]), "r"(a[2]), "r"(a[3]), "r"(b[0]), "r"(b[1]));
}

// ---------------- kernel 0: zero counters ----------------
__global__ void zero_kernel() {
    int t = threadIdx.x;
    if (t < NEXP) { g_counts[t] = 0; g_cursor[t] = 0; }
}

// ---------------- kernel 1: embed gather + mean pool ----------------
__global__ __launch_bounds__(256) void embed_pool_kernel(
    const int* __restrict__ x, const float* __restrict__ embed)
{
    __shared__ int sidx[SLEN];
    int b = blockIdx.x;
    int t = threadIdx.x;
    if (t < SLEN) sidx[t] = x[(size_t)b * SLEN + t];
    __syncthreads();
    const float4* e4 = reinterpret_cast<const float4*>(embed);
    float4 acc = make_float4(0.f, 0.f, 0.f, 0.f);
#pragma unroll 4
    for (int s = 0; s < SLEN; s++) {
        float4 v = __ldg(&e4[(size_t)sidx[s] * (DDIM / 4) + t]);
        acc.x += v.x; acc.y += v.y; acc.z += v.z; acc.w += v.w;
    }
    const float inv = 1.0f / (float)SLEN;
    float4 o = make_float4(acc.x * inv, acc.y * inv, acc.z * inv, acc.w * inv);
    reinterpret_cast<float4*>(g_h)[(size_t)b * (DDIM / 4) + t] = o;
}

// ---------------- kernel 2: gate, softmax, top-2 ----------------
__global__ __launch_bounds__(256) void gate_kernel(
    const float* __restrict__ gate_w, const float* __restrict__ gate_b,
    float* out_idx /* may be null */)
{
    int warp = threadIdx.x >> 5, lane = threadIdx.x & 31;
    int b = blockIdx.x * 8 + warp;
    float acc[NEXP];
#pragma unroll
    for (int e = 0; e < NEXP; e++) acc[e] = 0.f;
    const float* hrow = g_h + (size_t)b * DDIM;
    for (int d = lane; d < DDIM; d += 32) {
        float hv = hrow[d];
        const float4* gw4 = reinterpret_cast<const float4*>(gate_w + (size_t)d * NEXP);
        float4 g0 = gw4[0], g1 = gw4[1], g2 = gw4[2], g3 = gw4[3];
        acc[0]  += hv * g0.x; acc[1]  += hv * g0.y; acc[2]  += hv * g0.z; acc[3]  += hv * g0.w;
        acc[4]  += hv * g1.x; acc[5]  += hv * g1.y; acc[6]  += hv * g1.z; acc[7]  += hv * g1.w;
        acc[8]  += hv * g2.x; acc[9]  += hv * g2.y; acc[10] += hv * g2.z; acc[11] += hv * g2.w;
        acc[12] += hv * g3.x; acc[13] += hv * g3.y; acc[14] += hv * g3.z; acc[15] += hv * g3.w;
    }
#pragma unroll
    for (int off = 16; off > 0; off >>= 1)
#pragma unroll
        for (int e = 0; e < NEXP; e++) acc[e] += __shfl_xor_sync(0xffffffffu, acc[e], off);

    if (lane == 0) {
        float s[NEXP];
        float m = -3.4e38f;
#pragma unroll
        for (int e = 0; e < NEXP; e++) { s[e] = acc[e] + gate_b[e]; m = fmaxf(m, s[e]); }
        float se = 0.f, ex[NEXP];
#pragma unroll
        for (int e = 0; e < NEXP; e++) { ex[e] = __expf(s[e] - m); se += ex[e]; }
        // top-1 (strict > keeps lowest index on ties, matching lax.top_k)
        int i0 = 0; float v0 = s[0];
#pragma unroll
        for (int e = 1; e < NEXP; e++) if (s[e] > v0) { v0 = s[e]; i0 = e; }
        int i1 = -1; float v1 = -3.4e38f;
#pragma unroll
        for (int e = 0; e < NEXP; e++) if (e != i0 && s[e] > v1) { v1 = s[e]; i1 = e; }
        float inv_se = 1.f / se;
        float p0 = ex[i0] * inv_se, p1 = ex[i1] * inv_se;
        atomicAdd(&g_counts[i0], 1);
        atomicAdd(&g_counts[i1], 1);
        g_top_e[b * 2 + 0] = i0; g_top_p[b * 2 + 0] = p0;
        g_top_e[b * 2 + 1] = i1; g_top_p[b * 2 + 1] = p1;
        if (out_idx) {
            out_idx[(size_t)b * 2 + 0] = (float)i0;
            out_idx[(size_t)b * 2 + 1] = (float)i1;
        }
    }
}

// ---------------- kernel 3: exclusive prefix over 16 counts ----------------
__global__ void offsets_kernel() {
    if (threadIdx.x == 0) {
        int o = 0;
        for (int e = 0; e < NEXP; e++) { g_offsets[e] = o; o += g_counts[e]; }
    }
}

// ---------------- kernel 4: fill expert-grouped row lists ----------------
__global__ void fill_kernel() {
    int i = blockIdx.x * blockDim.x + threadIdx.x;
    if (i >= NROWS) return;
    int b = i >> 1, k = i & 1;
    int e = g_top_e[i];
    float p = g_top_p[i];
    int pos = atomicAdd(&g_cursor[e], 1);
    int r = g_offsets[e] + pos;
    g_row_token[r] = b;
    g_row_wgt[r] = p;
    g_row_slot[r] = k;
}

// ---------------- grouped GEMM (tf32 mma.sync, 128x128x32 tiles) ----------------
// PHASE1: C1[r, HDIM] = relu( H[tok(r)] @ W1[e] + b1[e] )
// PHASE2: parts[slot(r)][tok(r)] = wgt(r) * ( C1[r] @ W2[e] + b2[e] )
template<int KDIM, int NDIM, bool PHASE1>
__global__ __launch_bounds__(256, 1) void moe_gemm_kernel(
    const float* __restrict__ W, const float* __restrict__ bias)
{
    constexpr int ASZ = 128 * 36;   // floats per A stage (BKpad=36)
    constexpr int BSZ = 32 * 136;   // floats per B stage (BNpad=136)
    extern __shared__ float smem[];
    float* sA = smem;
    float* sB = smem + 2 * ASZ;
    __shared__ const float* sRowPtr[128];

    const int e = blockIdx.z;
    const int cnt = g_counts[e];
    const int mt0 = blockIdx.y * 128;
    if (mt0 >= cnt) return;
    const int off = g_offsets[e];
    const int nt0 = blockIdx.x * 128;
    const int tid = threadIdx.x;

    if (tid < 128) {
        int m = mt0 + tid;
        int mm = (m < cnt) ? m : (cnt - 1);
        if (PHASE1) sRowPtr[tid] = g_h + (size_t)g_row_token[off + mm] * DDIM;
        else        sRowPtr[tid] = g_c1 + (size_t)(off + mm) * HDIM;
    }
    __syncthreads();

    // loaders
    const int ar = tid >> 3, ac = (tid & 7) * 4;          // A: 8 thr/row, 4 rows each
    const float* ap[4];
#pragma unroll
    for (int i = 0; i < 4; i++) ap[i] = sRowPtr[ar + i * 32] + ac;
    const int bkr = tid & 31, bc = (tid >> 5) * 4;        // B: 32 rows, 8 col-groups
    const float* bp = W + (size_t)e * KDIM * NDIM + (size_t)bkr * NDIM + nt0 + bc;

    const unsigned saB = (unsigned)__cvta_generic_to_shared(sA);
    const unsigned sbB = (unsigned)__cvta_generic_to_shared(sB);

    auto load = [&](int stg, int k0) {
        unsigned da = saB + (unsigned)(stg * ASZ + ar * 36 + ac) * 4u;
#pragma unroll
        for (int i = 0; i < 4; i++) cp_async16(da + (unsigned)(i * 32 * 36) * 4u, ap[i] + k0);
        unsigned db = sbB + (unsigned)(stg * BSZ + bkr * 136 + bc) * 4u;
        const float* g = bp + (size_t)k0 * NDIM;
#pragma unroll
        for (int i = 0; i < 4; i++) cp_async16(db + (unsigned)(i * 32) * 4u, g + i * 32);
        cp_commit();
    };

    float c[2][8][4];
#pragma unroll
    for (int a = 0; a < 2; a++)
#pragma unroll
        for (int b2 = 0; b2 < 8; b2++)
#pragma unroll
            for (int k = 0; k < 4; k++) c[a][b2][k] = 0.f;

    const int wid = tid >> 5, lane = tid & 31;
    const int wm = wid & 3, wn = wid >> 2;          // 4x2 warp grid, warp tile 32x64
    const int arow = wm * 32 + (lane >> 2);
    const int klo  = lane & 3;
    const int bcol = wn * 64 + (lane >> 2);

    load(0, 0);
    constexpr int KT = KDIM / 32;
    for (int kt = 0; kt < KT; ++kt) {
        if (kt + 1 < KT) { load((kt + 1) & 1, (kt + 1) * 32); cp_wait<1>(); }
        else             { cp_wait<0>(); }
        __syncthreads();
        const float* A  = sA + (kt & 1) * ASZ;
        const float* Bm = sB + (kt & 1) * BSZ;
#pragma unroll
        for (int ks = 0; ks < 4; ++ks) {
            unsigned af[2][4];
#pragma unroll
            for (int m2 = 0; m2 < 2; m2++) {
                const float* a = A + (arow + m2 * 16) * 36 + ks * 8 + klo;
                af[m2][0] = f2tf32(a[0]);
                af[m2][1] = f2tf32(a[8 * 36]);
                af[m2][2] = f2tf32(a[4]);
                af[m2][3] = f2tf32(a[8 * 36 + 4]);
            }
            unsigned bf[8][2];
            const float* bb = Bm + (ks * 8 + klo) * 136 + bcol;
#pragma unroll
            for (int n2 = 0; n2 < 8; n2++) {
                bf[n2][0] = __float_as_uint(bb[n2 * 8]);
                bf[n2][1] = __float_as_uint(bb[4 * 136 + n2 * 8]);
            }
#pragma unroll
            for (int m2 = 0; m2 < 2; m2++)
#pragma unroll
                for (int n2 = 0; n2 < 8; n2++)
                    mma_tf32(c[m2][n2], af[m2], bf[n2]);
        }
        __syncthreads();
    }

    // epilogue
#pragma unroll
    for (int m2 = 0; m2 < 2; m2++) {
#pragma unroll
        for (int half = 0; half < 2; half++) {
            int grow = mt0 + wm * 32 + m2 * 16 + (lane >> 2) + half * 8;
            if (grow >= cnt) continue;
            int r = off + grow;
            if (PHASE1) {
                float* dst = g_c1 + (size_t)r * HDIM;
#pragma unroll
                for (int n2 = 0; n2 < 8; n2++) {
                    int col = nt0 + wn * 64 + n2 * 8 + (lane & 3) * 2;
                    float bv0 = bias[(size_t)e * NDIM + col];
                    float bv1 = bias[(size_t)e * NDIM + col + 1];
                    dst[col]     = fmaxf(c[m2][n2][half * 2 + 0] + bv0, 0.f);
                    dst[col + 1] = fmaxf(c[m2][n2][half * 2 + 1] + bv1, 0.f);
                }
            } else {
                int tok = g_row_token[r];
                int slot = g_row_slot[r];
                float w = g_row_wgt[r];
                float* dst = g_parts + (size_t)slot * BTOK * DDIM + (size_t)tok * DDIM;
#pragma unroll
                for (int n2 = 0; n2 < 8; n2++) {
                    int col = nt0 + wn * 64 + n2 * 8 + (lane & 3) * 2;
                    float bv0 = bias[(size_t)e * NDIM + col];
                    float bv1 = bias[(size_t)e * NDIM + col + 1];
                    dst[col]     = w * (c[m2][n2][half * 2 + 0] + bv0);
                    dst[col + 1] = w * (c[m2][n2][half * 2 + 1] + bv1);
                }
            }
        }
    }
}

// ---------------- kernel 7: combine slots + LayerNorm + head ----------------
__global__ __launch_bounds__(256) void lnhead_kernel(
    const float* __restrict__ ln_g, const float* __restrict__ ln_b,
    const float* __restrict__ head_w, const float* __restrict__ head_b,
    float* __restrict__ out)
{
    __shared__ float sx[DDIM];
    __shared__ float sred[2][8];
    __shared__ float shead[8][20];
    const int b = blockIdx.x, t = threadIdx.x;
    const int lane = t & 31, wid = t >> 5;

    float4 a = reinterpret_cast<const float4*>(g_parts + (size_t)b * DDIM)[t];
    float4 d = reinterpret_cast<const float4*>(g_parts + (size_t)(BTOK + b) * DDIM)[t];
    float4 v = make_float4(a.x + d.x, a.y + d.y, a.z + d.z, a.w + d.w);
    reinterpret_cast<float4*>(sx)[t] = v;
    float s  = v.x + v.y + v.z + v.w;
    float sq = v.x * v.x + v.y * v.y + v.z * v.z + v.w * v.w;
#pragma unroll
    for (int off = 16; off > 0; off >>= 1) {
        s  += __shfl_xor_sync(0xffffffffu, s, off);
        sq += __shfl_xor_sync(0xffffffffu, sq, off);
    }
    if (lane == 0) { sred[0][wid] = s; sred[1][wid] = sq; }
    __syncthreads();
    if (t == 0) {
        float ts = 0.f, tq = 0.f;
#pragma unroll
        for (int w = 0; w < 8; w++) { ts += sred[0][w]; tq += sred[1][w]; }
        float mu = ts / (float)DDIM;
        float var = tq / (float)DDIM - mu * mu;
        sred[0][0] = mu;
        sred[1][0] = rsqrtf(var + LN_EPS);
    }
    __syncthreads();
    const float mu = sred[0][0], rstd = sred[1][0];

    float lg[20];
#pragma unroll
    for (int o = 0; o < 20; o++) lg[o] = 0.f;
#pragma unroll
    for (int j = 0; j < 4; j++) {
        int di = t * 4 + j;
        float nx = (sx[di] - mu) * rstd * ln_g[di] + ln_b[di];
        const float* hw = head_w + (size_t)di * 20;
#pragma unroll
        for (int o = 0; o < 20; o++) lg[o] += nx * hw[o];
    }
#pragma unroll
    for (int off = 16; off > 0; off >>= 1)
#pragma unroll
        for (int o = 0; o < 20; o++) lg[o] += __shfl_xor_sync(0xffffffffu, lg[o], off);
    if (lane == 0)
#pragma unroll
        for (int o = 0; o < 20; o++) shead[wid][o] = lg[o];
    __syncthreads();
    if (wid == 0 && lane < 20) {
        float v2 = 0.f;
#pragma unroll
        for (int w = 0; w < 8; w++) v2 += shead[w][lane];
        out[(size_t)b * 20 + lane] = v2 + head_b[lane];
    }
}

// ---------------- launcher ----------------
extern "C" void kernel_launch(void* const* d_in, const int* in_sizes, int n_in,
                              void* d_out, int out_size)
{
    const int*   x      = (const int*)  d_in[0];
    const float* embed  = (const float*)d_in[1];
    const float* gate_w = (const float*)d_in[2];
    const float* gate_b = (const float*)d_in[3];
    const float* w1     = (const float*)d_in[4];
    const float* b1     = (const float*)d_in[5];
    const float* w2     = (const float*)d_in[6];
    const float* b2     = (const float*)d_in[7];
    const float* ln_g   = (const float*)d_in[8];
    const float* ln_b   = (const float*)d_in[9];
    const float* head_w = (const float*)d_in[10];
    const float* head_b = (const float*)d_in[11];
    float* out = (float*)d_out;

    const int SMEM_BYTES = (2 * 128 * 36 + 2 * 32 * 136) * 4; // 71,680 B
    cudaFuncSetAttribute((const void*)moe_gemm_kernel<DDIM, HDIM, true>,
                         cudaFuncAttributeMaxDynamicSharedMemorySize, SMEM_BYTES);
    cudaFuncSetAttribute((const void*)moe_gemm_kernel<HDIM, DDIM, false>,
                         cudaFuncAttributeMaxDynamicSharedMemorySize, SMEM_BYTES);

    // topk_idx region (cast to float) follows logits if the buffer is sized for both
    float* out_idx = (out_size >= BTOK * 20 + BTOK * TOPK) ? (out + BTOK * 20) : nullptr;

    zero_kernel<<<1, 32>>>();
    embed_pool_kernel<<<BTOK, 256>>>(x, embed);
    gate_kernel<<<BTOK / 8, 256>>>(gate_w, gate_b, out_idx);
    offsets_kernel<<<1, 1>>>();
    fill_kernel<<<(NROWS + 255) / 256, 256>>>();
    moe_gemm_kernel<DDIM, HDIM, true><<<dim3(HDIM / 128, 16, NEXP), 256, SMEM_BYTES>>>(w1, b1);
    moe_gemm_kernel<HDIM, DDIM, false><<<dim3(DDIM / 128, 16, NEXP), 256, SMEM_BYTES>>>(w2, b2);
    lnhead_kernel<<<BTOK, 256>>>(ln_g, ln_b, head_w, head_b, out);
}

// round 5
// speedup vs baseline: 1.1073x; 1.1073x over previous
#include <cuda_runtime.h>
#include <math.h>
#include <stdint.h>

#define VOCAB   32000
#define DDIM    1024
#define NEXP    16
#define TOPK    2
#define BTOK    2048
#define SLEN    128
#define HDIM    2048
#define LN_EPS  1e-5f
#define NROWS   (BTOK*TOPK)   // 4096 routed rows

// tcgen05 is arch-SPECIFIC (sm_103a/sm_100a). The harness also builds a
// generic sm_103 target where tcgen05 is illegal -> guard and provide an
// mma.sync fallback body for that pass (runtime prefers the specific cubin).
#if defined(__CUDA_ARCH_FEAT_SM103_ALL) || defined(__CUDA_ARCH_FEAT_SM100_ALL) || \
    defined(__CUDA_ARCH_FEAT_SM101_ALL) || \
    (defined(__CUDA_ARCH_SPECIFIC__) && (__CUDA_ARCH_SPECIFIC__ >= 1000)) || \
    (defined(__CUDA_ARCH_FAMILY_SPECIFIC__) && (__CUDA_ARCH_FAMILY_SPECIFIC__ >= 1000))
#define HAS_TCGEN05 1
#else
#define HAS_TCGEN05 0
#endif

// ---------------- scratch (device globals; no allocation) ----------------
__device__ float g_h[BTOK * DDIM];              // pooled embeddings (fp32 exact, for gate)
__device__ float g_h_r[BTOK * DDIM];            // tf32-rounded copy (GEMM1 A operand)
__device__ int   g_counts[NEXP];
__device__ int   g_offsets[NEXP];
__device__ int   g_cursor[NEXP];
__device__ int   g_top_e[NROWS];
__device__ float g_top_p[NROWS];
__device__ int   g_row_token[NROWS];
__device__ float g_row_wgt[NROWS];
__device__ int   g_row_slot[NROWS];
__device__ float g_c1[NROWS * HDIM];
__device__ float g_parts[TOPK * BTOK * DDIM];   // per-slot weighted outputs

// ---------------- small helpers ----------------
__device__ __forceinline__ uint32_t smem_u32(const void* p) {
    uint32_t a;
    asm("{ .reg .u64 t; cvta.to.shared.u64 t, %1; cvt.u32.u64 %0, t; }" : "=r"(a) : "l"(p));
    return a;
}
__device__ __forceinline__ unsigned f2tf32(float x) {
    unsigned y;
    asm("cvt.rna.tf32.f32 %0, %1;" : "=r"(y) : "f"(x));
    return y;
}
__device__ __forceinline__ void cp_async16(unsigned dst, const void* src) {
    asm volatile("cp.async.cg.shared.global [%0], [%1], 16;\n" :: "r"(dst), "l"(src));
}
__device__ __forceinline__ void cp_commit() { asm volatile("cp.async.commit_group;\n"); }
template<int N> __device__ __forceinline__ void cp_wait() {
    asm volatile("cp.async.wait_group %0;\n" :: "n"(N));
}

#define SMEM_SWIZZLE_128B(byte_offset) \
    ((byte_offset) ^ (((byte_offset) >> 3) & 0x70))

static constexpr uint64_t SMEM_DESC_BASE_SW128 =
    (uint64_t(2)  << 61) | (uint64_t(1) << 46) | (uint64_t(64) << 32) | (uint64_t(1) << 16);
#define MAKE_SMEM_DESC(base_addr) \
    (SMEM_DESC_BASE_SW128 | ((uint64_t)((base_addr) >> 4) & 0x3FFF))

#if HAS_TCGEN05
#define TCGEN05_ALLOC(smem_result_addr, nCols) \
    asm volatile("tcgen05.alloc.cta_group::1.sync.aligned.shared::cta.b32 [%0], %1;" \
        :: "r"((uint32_t)(smem_result_addr)), "r"((uint32_t)(nCols)) : "memory")
#define TCGEN05_DEALLOC(tmem_addr, nCols) \
    asm volatile("tcgen05.dealloc.cta_group::1.sync.aligned.b32 %0, %1;" \
        :: "r"(tmem_addr), "r"((uint32_t)(nCols)))
#define TCGEN05_RELINQUISH() \
    asm volatile("tcgen05.relinquish_alloc_permit.cta_group::1.sync.aligned;")
#define TCGEN05_COMMIT(mbar_smem_addr) \
    asm volatile("tcgen05.commit.cta_group::1.mbarrier::arrive::one.shared::cluster.b64 [%0];" \
        :: "r"((uint32_t)(mbar_smem_addr)) : "memory")
#define TCGEN05_FENCE_AFTER() \
    asm volatile("tcgen05.fence::after_thread_sync;" ::: "memory")
#define TCGEN05_FENCE_BEFORE() \
    asm volatile("tcgen05.fence::before_thread_sync;" ::: "memory")
#define TCGEN05_WAIT_LD() \
    asm volatile("tcgen05.wait::ld.sync.aligned;" ::: "memory")
#define FENCE_PROXY_ASYNC_SHARED_CTA() \
    asm volatile("fence.proxy.async.shared::cta;" ::: "memory")
#define MBARRIER_INIT(mbar_smem_addr, count) \
    asm volatile("mbarrier.init.shared.b64 [%0], %1;" \
        :: "r"((uint32_t)(mbar_smem_addr)), "r"((uint32_t)(count)) : "memory")
#define MBARRIER_WAIT_PARITY(mbar_smem_addr, phase_parity) do { \
    uint32_t _mbar = (uint32_t)(mbar_smem_addr); \
    uint32_t _parity = (uint32_t)(phase_parity); \
    uint32_t _done; \
    asm volatile( \
        "{\n\t" \
        ".reg .pred p;\n\t" \
        "mbarrier.try_wait.parity.acquire.cta.shared::cta.b64 p, [%1], %2;\n\t" \
        "selp.b32 %0, 1, 0, p;\n\t" \
        "}" \
        : "=r"(_done) : "r"(_mbar), "r"(_parity) : "memory"); \
    if (!_done) { \
        asm volatile( \
            "{\n\t" \
            ".reg .pred P1;\n\t" \
            "WAIT_LOOP_%=:\n\t" \
            "mbarrier.try_wait.parity.acquire.cta.shared::cta.b64 P1, [%0], %1, 0x989680;\n\t" \
            "@P1 bra.uni WAIT_DONE_%=;\n\t" \
            "bra.uni WAIT_LOOP_%=;\n\t" \
            "WAIT_DONE_%=:\n\t" \
            "}" \
            :: "r"(_mbar), "r"(_parity) : "memory"); \
    } \
} while(0)

#define TCGEN05_LD_32X32B_X32(r, tmem_addr) \
    asm volatile( \
        "tcgen05.ld.sync.aligned.32x32b.x32.b32 " \
        "{%0, %1, %2, %3, %4, %5, %6, %7, " \
        " %8, %9, %10, %11, %12, %13, %14, %15, " \
        " %16, %17, %18, %19, %20, %21, %22, %23, " \
        " %24, %25, %26, %27, %28, %29, %30, %31}, [%32];" \
        : "=r"((r)[0]),  "=r"((r)[1]),  "=r"((r)[2]),  "=r"((r)[3]), \
          "=r"((r)[4]),  "=r"((r)[5]),  "=r"((r)[6]),  "=r"((r)[7]), \
          "=r"((r)[8]),  "=r"((r)[9]),  "=r"((r)[10]), "=r"((r)[11]), \
          "=r"((r)[12]), "=r"((r)[13]), "=r"((r)[14]), "=r"((r)[15]), \
          "=r"((r)[16]), "=r"((r)[17]), "=r"((r)[18]), "=r"((r)[19]), \
          "=r"((r)[20]), "=r"((r)[21]), "=r"((r)[22]), "=r"((r)[23]), \
          "=r"((r)[24]), "=r"((r)[25]), "=r"((r)[26]), "=r"((r)[27]), \
          "=r"((r)[28]), "=r"((r)[29]), "=r"((r)[30]), "=r"((r)[31]) \
        : "r"(tmem_addr))

__device__ __forceinline__ void tcgen05_mma_tf32_ss(
    uint32_t d_tmem, uint64_t a_desc, uint64_t b_desc, uint32_t idesc, bool acc)
{
    uint32_t en = acc ? 1u : 0u;
    asm volatile(
        "{\n\t"
        ".reg .pred p;\n\t"
        "setp.ne.u32 p, %5, 0;\n\t"
        "tcgen05.mma.cta_group::1.kind::tf32 [%0], %1, %2, %3, {%4, %4, %4, %4}, p;\n\t"
        "}"
        :: "r"(d_tmem), "l"(a_desc), "l"(b_desc), "r"(idesc), "r"(0u), "r"(en)
        : "memory");
}
#endif // HAS_TCGEN05

#define STS128U(r0, r1, r2, r3, smem_addr) \
    asm volatile("st.shared.v4.b32 [%0], {%1, %2, %3, %4};" \
        :: "r"(smem_addr), "r"(r0), "r"(r1), "r"(r2), "r"(r3) : "memory")

__device__ __forceinline__ void mma_tf32_fb(float c[4], const unsigned a[4], const unsigned b[2]) {
    asm volatile(
        "mma.sync.aligned.m16n8k8.row.col.f32.tf32.tf32.f32 "
        "{%0,%1,%2,%3}, {%4,%5,%6,%7}, {%8,%9}, {%0,%1,%2,%3};\n"
        : "+f"(c[0]), "+f"(c[1]), "+f"(c[2]), "+f"(c[3])
        : "r"(a[0]), "r"(a[1]), "r"(a[2]), "r"(a[3]), "r"(b[0]), "r"(b[1]));
}

// ---------------- kernel 0: zero counters ----------------
__global__ void zero_kernel() {
    int t = threadIdx.x;
    if (t < NEXP) { g_counts[t] = 0; g_cursor[t] = 0; }
}

// ---------------- kernel 1: embed gather + mean pool ----------------
__global__ __launch_bounds__(256) void embed_pool_kernel(
    const int* __restrict__ x, const float* __restrict__ embed)
{
    __shared__ int sidx[SLEN];
    int b = blockIdx.x;
    int t = threadIdx.x;
    if (t < SLEN) sidx[t] = x[(size_t)b * SLEN + t];
    __syncthreads();
    const float4* e4 = reinterpret_cast<const float4*>(embed);
    float4 acc = make_float4(0.f, 0.f, 0.f, 0.f);
#pragma unroll 4
    for (int s = 0; s < SLEN; s++) {
        float4 v = __ldg(&e4[(size_t)sidx[s] * (DDIM / 4) + t]);
        acc.x += v.x; acc.y += v.y; acc.z += v.z; acc.w += v.w;
    }
    const float inv = 1.0f / (float)SLEN;
    float4 o = make_float4(acc.x * inv, acc.y * inv, acc.z * inv, acc.w * inv);
    reinterpret_cast<float4*>(g_h)[(size_t)b * (DDIM / 4) + t] = o;
    float4 orn;
    orn.x = __uint_as_float(f2tf32(o.x));
    orn.y = __uint_as_float(f2tf32(o.y));
    orn.z = __uint_as_float(f2tf32(o.z));
    orn.w = __uint_as_float(f2tf32(o.w));
    reinterpret_cast<float4*>(g_h_r)[(size_t)b * (DDIM / 4) + t] = orn;
}

// ---------------- kernel 2: gate, softmax, top-2 ----------------
__global__ __launch_bounds__(256) void gate_kernel(
    const float* __restrict__ gate_w, const float* __restrict__ gate_b,
    float* out_idx /* may be null */)
{
    int warp = threadIdx.x >> 5, lane = threadIdx.x & 31;
    int b = blockIdx.x * 8 + warp;
    float acc[NEXP];
#pragma unroll
    for (int e = 0; e < NEXP; e++) acc[e] = 0.f;
    const float* hrow = g_h + (size_t)b * DDIM;
    for (int d = lane; d < DDIM; d += 32) {
        float hv = hrow[d];
        const float4* gw4 = reinterpret_cast<const float4*>(gate_w + (size_t)d * NEXP);
        float4 g0 = gw4[0], g1 = gw4[1], g2 = gw4[2], g3 = gw4[3];
        acc[0]  += hv * g0.x; acc[1]  += hv * g0.y; acc[2]  += hv * g0.z; acc[3]  += hv * g0.w;
        acc[4]  += hv * g1.x; acc[5]  += hv * g1.y; acc[6]  += hv * g1.z; acc[7]  += hv * g1.w;
        acc[8]  += hv * g2.x; acc[9]  += hv * g2.y; acc[10] += hv * g2.z; acc[11] += hv * g2.w;
        acc[12] += hv * g3.x; acc[13] += hv * g3.y; acc[14] += hv * g3.z; acc[15] += hv * g3.w;
    }
#pragma unroll
    for (int off = 16; off > 0; off >>= 1)
#pragma unroll
        for (int e = 0; e < NEXP; e++) acc[e] += __shfl_xor_sync(0xffffffffu, acc[e], off);

    if (lane == 0) {
        float s[NEXP];
        float m = -3.4e38f;
#pragma unroll
        for (int e = 0; e < NEXP; e++) { s[e] = acc[e] + gate_b[e]; m = fmaxf(m, s[e]); }
        float se = 0.f, ex[NEXP];
#pragma unroll
        for (int e = 0; e < NEXP; e++) { ex[e] = __expf(s[e] - m); se += ex[e]; }
        int i0 = 0; float v0 = s[0];
#pragma unroll
        for (int e = 1; e < NEXP; e++) if (s[e] > v0) { v0 = s[e]; i0 = e; }
        int i1 = -1; float v1 = -3.4e38f;
#pragma unroll
        for (int e = 0; e < NEXP; e++) if (e != i0 && s[e] > v1) { v1 = s[e]; i1 = e; }
        float inv_se = 1.f / se;
        float p0 = ex[i0] * inv_se, p1 = ex[i1] * inv_se;
        atomicAdd(&g_counts[i0], 1);
        atomicAdd(&g_counts[i1], 1);
        g_top_e[b * 2 + 0] = i0; g_top_p[b * 2 + 0] = p0;
        g_top_e[b * 2 + 1] = i1; g_top_p[b * 2 + 1] = p1;
        if (out_idx) {
            out_idx[(size_t)b * 2 + 0] = (float)i0;
            out_idx[(size_t)b * 2 + 1] = (float)i1;
        }
    }
}

// ---------------- kernel 3: exclusive prefix over 16 counts ----------------
__global__ void offsets_kernel() {
    if (threadIdx.x == 0) {
        int o = 0;
        for (int e = 0; e < NEXP; e++) { g_offsets[e] = o; o += g_counts[e]; }
    }
}

// ---------------- kernel 4: fill expert-grouped row lists ----------------
__global__ void fill_kernel() {
    int i = blockIdx.x * blockDim.x + threadIdx.x;
    if (i >= NROWS) return;
    int b = i >> 1, k = i & 1;
    int e = g_top_e[i];
    float p = g_top_p[i];
    int pos = atomicAdd(&g_cursor[e], 1);
    int r = g_offsets[e] + pos;
    g_row_token[r] = b;
    g_row_wgt[r] = p;
    g_row_slot[r] = k;
}

// ---------------- grouped GEMM ----------------
// blockIdx.x = M-tile (128 routed rows), blockIdx.y = N-tile (128), blockIdx.z = expert
// sm_103a pass: tcgen05 tf32 SS MMA, TMEM accumulator.
// generic pass: mma.sync tf32 fallback (identical math contract).
template<int KDIM, int NDIM, bool PHASE1>
__global__ __launch_bounds__(256, 1) __cluster_dims__(1, 1, 1) void moe_gemm_tc(
    const float* __restrict__ W, const float* __restrict__ bias)
{
#if HAS_TCGEN05
    constexpr int KT  = KDIM / 32;
    constexpr int ASZ = 128 * 32;   // floats / A stage (16KB)
    constexpr int BSZ = 128 * 32;   // floats / swizzled-B stage (16KB)
    constexpr int RSZ = 32 * 132;   // floats / raw-B stage (16.9KB, padded rows)
    constexpr int RAW_OFF = 4 * ASZ + 2 * BSZ;

    __shared__ uint64_t s_mbar[2];
    __shared__ uint32_t s_tmem;
    __shared__ const float* sRowPtr[128];
    __shared__ float s_bias[128];

    const int e   = blockIdx.z;
    const int cnt = g_counts[e];
    const int mt0 = blockIdx.x * 128;
    if (mt0 >= cnt) return;
    const int off = g_offsets[e];
    const int nt0 = blockIdx.y * 128;
    const int tid = threadIdx.x;
    const int wid = tid >> 5, lane = tid & 31;

    extern __shared__ char dsm[];
    const uint32_t rawb  = smem_u32(dsm);
    const uint32_t abase = (rawb + 1023u) & ~1023u;
    float* SB = (float*)(dsm + (abase - rawb));

    if (wid == 0) TCGEN05_ALLOC(smem_u32(&s_tmem), 128);
    if (tid == 0) {
        MBARRIER_INIT(smem_u32(&s_mbar[0]), 1);
        MBARRIER_INIT(smem_u32(&s_mbar[1]), 1);
    }
    if (tid < 128) {
        int mm = mt0 + tid; if (mm >= cnt) mm = cnt - 1;
        if (PHASE1) sRowPtr[tid] = g_h_r + (size_t)g_row_token[off + mm] * DDIM;
        else        sRowPtr[tid] = g_c1 + (size_t)(off + mm) * (size_t)KDIM;
        s_bias[tid] = bias[(size_t)e * NDIM + nt0 + tid];
    }
    __syncthreads();
    if (wid == 0) TCGEN05_RELINQUISH();
    const uint32_t tmem = s_tmem;
    const uint32_t mb0 = smem_u32(&s_mbar[0]);
    const uint32_t mb1 = smem_u32(&s_mbar[1]);

    const int arow   = tid >> 1;
    const int ahalfB = (tid & 1) * 64;
    const float* aptr = sRowPtr[arow] + ahalfB / 4;
    const int bkr = tid >> 3;
    const int bnf = (tid & 7) * 16;
    const float* wptr = W + (size_t)e * KDIM * NDIM + (size_t)bkr * NDIM + nt0 + bnf;

    auto load_chunk = [&](int kt) {
        const int st = kt & 3;
        const int k0 = kt * 32;
        uint32_t ab = abase + (uint32_t)(st * ASZ) * 4u;
        const float* ap = aptr + k0;
#pragma unroll
        for (int i = 0; i < 4; i++) {
            uint32_t doff = (uint32_t)(arow * 128 + ahalfB + i * 16);
            cp_async16(ab + SMEM_SWIZZLE_128B(doff), ap + i * 4);
        }
        uint32_t bb = abase + (uint32_t)(RAW_OFF + st * RSZ + bkr * 132 + bnf) * 4u;
        const float* bp = wptr + (size_t)k0 * NDIM;
#pragma unroll
        for (int i = 0; i < 4; i++) cp_async16(bb + (uint32_t)(i * 16), bp + i * 4);
        cp_commit();
    };

    const int tn  = tid >> 1;
    const int tkh = (tid & 1) * 16;
    auto transpose_chunk = [&](int kt) {
        const float* rp = SB + RAW_OFF + (kt & 3) * RSZ;
        uint32_t bd = abase + (uint32_t)(4 * ASZ + (kt & 1) * BSZ) * 4u;
        unsigned v[16];
#pragma unroll
        for (int j = 0; j < 16; j++) v[j] = f2tf32(rp[(tkh + j) * 132 + tn]);
#pragma unroll
        for (int g = 0; g < 4; g++) {
            uint32_t doff = (uint32_t)(tn * 128 + (tkh + g * 4) * 4);
            STS128U(v[g * 4], v[g * 4 + 1], v[g * 4 + 2], v[g * 4 + 3],
                    bd + SMEM_SWIZZLE_128B(doff));
        }
    };

    // idesc: c=F32(1<<4), a=TF32(2<<7), b=TF32(2<<10), N=128(16<<17), M=128(8<<24)
    const uint32_t IDESC = (1u << 4) | (2u << 7) | (2u << 10) | (16u << 17) | (8u << 24);

    load_chunk(0);
    load_chunk(1);
    int ph0 = 0, ph1 = 0;

    for (int kt = 0; kt < KT; ++kt) {
        // FIX (round 4): at the final iteration only ONE group is in flight,
        // so wait_group 1 would NOT wait for chunk KT-1's data -> race.
        if (kt + 1 < KT) cp_wait<1>(); else cp_wait<0>();
        __syncthreads();
        if (kt >= 2) {
            if (kt & 1) { MBARRIER_WAIT_PARITY(mb1, ph1); ph1 ^= 1; }
            else        { MBARRIER_WAIT_PARITY(mb0, ph0); ph0 ^= 1; }
        }
        transpose_chunk(kt);
        FENCE_PROXY_ASYNC_SHARED_CTA();
        __syncthreads();
        if (tid == 0) {
            uint64_t ad = MAKE_SMEM_DESC(abase + (uint32_t)((kt & 3) * ASZ) * 4u);
            uint64_t bd = MAKE_SMEM_DESC(abase + (uint32_t)(4 * ASZ + (kt & 1) * BSZ) * 4u);
#pragma unroll
            for (int s = 0; s < 4; s++)
                tcgen05_mma_tf32_ss(tmem, ad + s * 2, bd + s * 2, IDESC, (kt > 0) || (s > 0));
            TCGEN05_COMMIT((kt & 1) ? mb1 : mb0);
        }
        if (kt + 2 < KT) load_chunk(kt + 2);
    }
    if ((KT - 1) & 1) { MBARRIER_WAIT_PARITY(mb1, ph1); }
    else              { MBARRIER_WAIT_PARITY(mb0, ph0); }
    TCGEN05_FENCE_AFTER();

    // epilogue: warps 0-3 cols [0,64), warps 4-7 cols [64,128)
    const int sp = wid & 3;
    const int cb = (wid >> 2) * 64;
    const int rloc = mt0 + sp * 32 + lane;
    const bool valid = rloc < cnt;
    const int r = off + (valid ? rloc : 0);
    float wgt = 0.f;
    float* dst;
    if (PHASE1) {
        dst = g_c1 + (size_t)r * NDIM;
    } else {
        int tok = valid ? g_row_token[r] : 0;
        int slt = valid ? g_row_slot[r] : 0;
        wgt = valid ? g_row_wgt[r] : 0.f;
        dst = g_parts + (size_t)slt * (BTOK * DDIM) + (size_t)tok * DDIM;
    }

#pragma unroll
    for (int g = 0; g < 2; g++) {
        unsigned regs[32];
        TCGEN05_LD_32X32B_X32(regs, tmem + cb + g * 32);
        TCGEN05_WAIT_LD();
        if (valid) {
#pragma unroll
            for (int q = 0; q < 8; q++) {
                int c = cb + g * 32 + q * 4;
                float x0 = __uint_as_float(regs[q * 4 + 0]) + s_bias[c + 0];
                float x1 = __uint_as_float(regs[q * 4 + 1]) + s_bias[c + 1];
                float x2 = __uint_as_float(regs[q * 4 + 2]) + s_bias[c + 2];
                float x3 = __uint_as_float(regs[q * 4 + 3]) + s_bias[c + 3];
                float4 o;
                if (PHASE1) {
                    o.x = __uint_as_float(f2tf32(fmaxf(x0, 0.f)));
                    o.y = __uint_as_float(f2tf32(fmaxf(x1, 0.f)));
                    o.z = __uint_as_float(f2tf32(fmaxf(x2, 0.f)));
                    o.w = __uint_as_float(f2tf32(fmaxf(x3, 0.f)));
                } else {
                    o.x = wgt * x0; o.y = wgt * x1; o.z = wgt * x2; o.w = wgt * x3;
                }
                *reinterpret_cast<float4*>(dst + nt0 + c) = o;
            }
        }
    }

    TCGEN05_FENCE_BEFORE();
    __syncthreads();
    if (wid == 0) TCGEN05_DEALLOC(tmem, 128);

#else  // ---------------- fallback: mma.sync tf32 (generic sm_103 pass) ----------------
    constexpr int ASZ = 128 * 36;
    constexpr int BSZ = 32 * 136;
    extern __shared__ char dsm[];
    float* sA = (float*)dsm;
    float* sB = (float*)dsm + 2 * ASZ;
    __shared__ const float* sRowPtr[128];

    const int e = blockIdx.z;
    const int cnt = g_counts[e];
    const int mt0 = blockIdx.x * 128;
    if (mt0 >= cnt) return;
    const int off = g_offsets[e];
    const int nt0 = blockIdx.y * 128;
    const int tid = threadIdx.x;

    if (tid < 128) {
        int m = mt0 + tid;
        int mm = (m < cnt) ? m : (cnt - 1);
        if (PHASE1) sRowPtr[tid] = g_h_r + (size_t)g_row_token[off + mm] * DDIM;
        else        sRowPtr[tid] = g_c1 + (size_t)(off + mm) * (size_t)KDIM;
    }
    __syncthreads();

    const int ar = tid >> 3, ac = (tid & 7) * 4;
    const float* ap[4];
#pragma unroll
    for (int i = 0; i < 4; i++) ap[i] = sRowPtr[ar + i * 32] + ac;
    const int bkr = tid & 31, bc = (tid >> 5) * 4;
    const float* bp = W + (size_t)e * KDIM * NDIM + (size_t)bkr * NDIM + nt0 + bc;

    const unsigned saB = (unsigned)__cvta_generic_to_shared(sA);
    const unsigned sbB = (unsigned)__cvta_generic_to_shared(sB);

    auto load = [&](int stg, int k0) {
        unsigned da = saB + (unsigned)(stg * ASZ + ar * 36 + ac) * 4u;
#pragma unroll
        for (int i = 0; i < 4; i++) cp_async16(da + (unsigned)(i * 32 * 36) * 4u, ap[i] + k0);
        unsigned db = sbB + (unsigned)(stg * BSZ + bkr * 136 + bc) * 4u;
        const float* g = bp + (size_t)k0 * NDIM;
#pragma unroll
        for (int i = 0; i < 4; i++) cp_async16(db + (unsigned)(i * 32) * 4u, g + i * 32);
        cp_commit();
    };

    float c[2][8][4];
#pragma unroll
    for (int a = 0; a < 2; a++)
#pragma unroll
        for (int b2 = 0; b2 < 8; b2++)
#pragma unroll
            for (int k = 0; k < 4; k++) c[a][b2][k] = 0.f;

    const int wid = tid >> 5, lane = tid & 31;
    const int wm = wid & 3, wn = wid >> 2;
    const int arow = wm * 32 + (lane >> 2);
    const int klo  = lane & 3;
    const int bcol = wn * 64 + (lane >> 2);

    load(0, 0);
    constexpr int KT = KDIM / 32;
    for (int kt = 0; kt < KT; ++kt) {
        if (kt + 1 < KT) { load((kt + 1) & 1, (kt + 1) * 32); cp_wait<1>(); }
        else             { cp_wait<0>(); }
        __syncthreads();
        const float* A  = sA + (kt & 1) * ASZ;
        const float* Bm = sB + (kt & 1) * BSZ;
#pragma unroll
        for (int ks = 0; ks < 4; ++ks) {
            unsigned af[2][4];
#pragma unroll
            for (int m2 = 0; m2 < 2; m2++) {
                const float* a = A + (arow + m2 * 16) * 36 + ks * 8 + klo;
                af[m2][0] = f2tf32(a[0]);
                af[m2][1] = f2tf32(a[8 * 36]);
                af[m2][2] = f2tf32(a[4]);
                af[m2][3] = f2tf32(a[8 * 36 + 4]);
            }
            unsigned bf[8][2];
            const float* bb = Bm + (ks * 8 + klo) * 136 + bcol;
#pragma unroll
            for (int n2 = 0; n2 < 8; n2++) {
                bf[n2][0] = f2tf32(bb[n2 * 8]);
                bf[n2][1] = f2tf32(bb[4 * 136 + n2 * 8]);
            }
#pragma unroll
            for (int m2 = 0; m2 < 2; m2++)
#pragma unroll
                for (int n2 = 0; n2 < 8; n2++)
                    mma_tf32_fb(c[m2][n2], af[m2], bf[n2]);
        }
        __syncthreads();
    }

#pragma unroll
    for (int m2 = 0; m2 < 2; m2++) {
#pragma unroll
        for (int half = 0; half < 2; half++) {
            int grow = mt0 + wm * 32 + m2 * 16 + (lane >> 2) + half * 8;
            if (grow >= cnt) continue;
            int r = off + grow;
            if (PHASE1) {
                float* dst = g_c1 + (size_t)r * NDIM;
#pragma unroll
                for (int n2 = 0; n2 < 8; n2++) {
                    int col = nt0 + wn * 64 + n2 * 8 + (lane & 3) * 2;
                    float bv0 = bias[(size_t)e * NDIM + col];
                    float bv1 = bias[(size_t)e * NDIM + col + 1];
                    dst[col]     = __uint_as_float(f2tf32(fmaxf(c[m2][n2][half * 2 + 0] + bv0, 0.f)));
                    dst[col + 1] = __uint_as_float(f2tf32(fmaxf(c[m2][n2][half * 2 + 1] + bv1, 0.f)));
                }
            } else {
                int tok = g_row_token[r];
                int slot = g_row_slot[r];
                float w = g_row_wgt[r];
                float* dst = g_parts + (size_t)slot * (BTOK * DDIM) + (size_t)tok * DDIM;
#pragma unroll
                for (int n2 = 0; n2 < 8; n2++) {
                    int col = nt0 + wn * 64 + n2 * 8 + (lane & 3) * 2;
                    float bv0 = bias[(size_t)e * NDIM + col];
                    float bv1 = bias[(size_t)e * NDIM + col + 1];
                    dst[col]     = w * (c[m2][n2][half * 2 + 0] + bv0);
                    dst[col + 1] = w * (c[m2][n2][half * 2 + 1] + bv1);
                }
            }
        }
    }
#endif
}

// ---------------- kernel 7: combine slots + LayerNorm + head ----------------
__global__ __launch_bounds__(256) void lnhead_kernel(
    const float* __restrict__ ln_g, const float* __restrict__ ln_b,
    const float* __restrict__ head_w, const float* __restrict__ head_b,
    float* __restrict__ out)
{
    __shared__ float sx[DDIM];
    __shared__ float sred[2][8];
    __shared__ float shead[8][20];
    const int b = blockIdx.x, t = threadIdx.x;
    const int lane = t & 31, wid = t >> 5;

    float4 a = reinterpret_cast<const float4*>(g_parts + (size_t)b * DDIM)[t];
    float4 d = reinterpret_cast<const float4*>(g_parts + (size_t)(BTOK + b) * DDIM)[t];
    float4 v = make_float4(a.x + d.x, a.y + d.y, a.z + d.z, a.w + d.w);
    reinterpret_cast<float4*>(sx)[t] = v;
    float s  = v.x + v.y + v.z + v.w;
    float sq = v.x * v.x + v.y * v.y + v.z * v.z + v.w * v.w;
#pragma unroll
    for (int off = 16; off > 0; off >>= 1) {
        s  += __shfl_xor_sync(0xffffffffu, s, off);
        sq += __shfl_xor_sync(0xffffffffu, sq, off);
    }
    if (lane == 0) { sred[0][wid] = s; sred[1][wid] = sq; }
    __syncthreads();
    if (t == 0) {
        float ts = 0.f, tq = 0.f;
#pragma unroll
        for (int w = 0; w < 8; w++) { ts += sred[0][w]; tq += sred[1][w]; }
        float mu = ts / (float)DDIM;
        float var = tq / (float)DDIM - mu * mu;
        sred[0][0] = mu;
        sred[1][0] = rsqrtf(var + LN_EPS);
    }
    __syncthreads();
    const float mu = sred[0][0], rstd = sred[1][0];

    float lg[20];
#pragma unroll
    for (int o = 0; o < 20; o++) lg[o] = 0.f;
#pragma unroll
    for (int j = 0; j < 4; j++) {
        int di = t * 4 + j;
        float nx = (sx[di] - mu) * rstd * ln_g[di] + ln_b[di];
        const float* hw = head_w + (size_t)di * 20;
#pragma unroll
        for (int o = 0; o < 20; o++) lg[o] += nx * hw[o];
    }
#pragma unroll
    for (int off = 16; off > 0; off >>= 1)
#pragma unroll
        for (int o = 0; o < 20; o++) lg[o] += __shfl_xor_sync(0xffffffffu, lg[o], off);
    if (lane == 0)
#pragma unroll
        for (int o = 0; o < 20; o++) shead[wid][o] = lg[o];
    __syncthreads();
    if (wid == 0 && lane < 20) {
        float v2 = 0.f;
#pragma unroll
        for (int w = 0; w < 8; w++) v2 += shead[w][lane];
        out[(size_t)b * 20 + lane] = v2 + head_b[lane];
    }
}

// ---------------- launcher ----------------
extern "C" void kernel_launch(void* const* d_in, const int* in_sizes, int n_in,
                              void* d_out, int out_size)
{
    const int*   x      = (const int*)  d_in[0];
    const float* embed  = (const float*)d_in[1];
    const float* gate_w = (const float*)d_in[2];
    const float* gate_b = (const float*)d_in[3];
    const float* w1     = (const float*)d_in[4];
    const float* b1     = (const float*)d_in[5];
    const float* w2     = (const float*)d_in[6];
    const float* b2     = (const float*)d_in[7];
    const float* ln_g   = (const float*)d_in[8];
    const float* ln_b   = (const float*)d_in[9];
    const float* head_w = (const float*)d_in[10];
    const float* head_b = (const float*)d_in[11];
    float* out = (float*)d_out;

    // dyn smem (tcgen05 path): 4 A stages + 2 B stages + 4 raw stages + align slack
    const int DSMEM = (4 * 128 * 32 + 2 * 128 * 32 + 4 * 32 * 132) * 4 + 1024;
    cudaFuncSetAttribute((const void*)moe_gemm_tc<DDIM, HDIM, true>,
                         cudaFuncAttributeMaxDynamicSharedMemorySize, DSMEM);
    cudaFuncSetAttribute((const void*)moe_gemm_tc<HDIM, DDIM, false>,
                         cudaFuncAttributeMaxDynamicSharedMemorySize, DSMEM);

    float* out_idx = (out_size >= BTOK * 20 + BTOK * TOPK) ? (out + BTOK * 20) : nullptr;

    zero_kernel<<<1, 32>>>();
    embed_pool_kernel<<<BTOK, 256>>>(x, embed);
    gate_kernel<<<BTOK / 8, 256>>>(gate_w, gate_b, out_idx);
    offsets_kernel<<<1, 1>>>();
    fill_kernel<<<(NROWS + 255) / 256, 256>>>();
    moe_gemm_tc<DDIM, HDIM, true><<<dim3(16, HDIM / 128, NEXP), 256, DSMEM>>>(w1, b1);
    moe_gemm_tc<HDIM, DDIM, false><<<dim3(16, DDIM / 128, NEXP), 256, DSMEM>>>(w2, b2);
    lnhead_kernel<<<BTOK, 256>>>(ln_g, ln_b, head_w, head_b, out);
}